// round 9
// baseline (speedup 1.0000x reference)
#include <cuda_runtime.h>

// tokens: int32[4194304] (values in [0,128)), ls: float32[128,2,2], final (unused)
// output: float32[2] = row 0 of ordered product of ls[tokens[t]], last token applied twice.

#define TPB 256
#define TOK_PER_THREAD 16
#define TOK_PER_BLOCK (TPB * TOK_PER_THREAD)   // 4096
#define MAX_BLOCKS 4096
#define GROUP_SHIFT 5
#define NGROUPS 32

__device__ float4 g_part[MAX_BLOCKS];
__device__ unsigned g_cnt[(NGROUPS + 1) * 64];   // 256B-spaced counters + root

__device__ __forceinline__ unsigned atom_inc_acqrel(unsigned* p) {
    unsigned old;
    asm volatile("atom.add.acq_rel.gpu.global.u32 %0, [%1], %2;"
                 : "=r"(old) : "l"(p), "r"(1u) : "memory");
    return old;
}

// C = A @ B, row-major 2x2 packed in float4 (x=m00, y=m01, z=m10, w=m11)
__device__ __forceinline__ float4 mm2(float4 A, float4 B) {
    float4 C;
    C.x = fmaf(A.x, B.x, A.y * B.z);
    C.y = fmaf(A.x, B.y, A.y * B.w);
    C.z = fmaf(A.z, B.x, A.w * B.z);
    C.w = fmaf(A.z, B.y, A.w * B.w);
    return C;
}

// Order-preserving pairwise warp reduction; lane 0 ends with ordered product.
__device__ __forceinline__ float4 warp_reduce_ordered(float4 M, unsigned lane) {
    #pragma unroll
    for (int off = 1; off < 32; off <<= 1) {
        float4 B;
        B.x = __shfl_down_sync(0xffffffffu, M.x, off);
        B.y = __shfl_down_sync(0xffffffffu, M.y, off);
        B.z = __shfl_down_sync(0xffffffffu, M.z, off);
        B.w = __shfl_down_sync(0xffffffffu, M.w, off);
        if ((lane & (2 * off - 1)) == 0) M = mm2(M, B);
    }
    return M;
}

// 16B-granule swizzle: conflict-free-ish on tid-major write AND 8l+k read.
__device__ __forceinline__ unsigned swz(unsigned i) { return i ^ ((i >> 3) & 7u); }

__global__ void __launch_bounds__(TPB)
chain_fused_kernel(const int* __restrict__ tokens,
                   const float* __restrict__ ls,
                   float* __restrict__ out,
                   int n_tokens) {
    // Replicated table: entry j, replica r at byte j*128 + r*16.
    // Lane l reads replica (l&7) -> fixed bank group, uniform 4-way = floor.
    __shared__ __align__(16) char  s_tab[128 * 128];          // 16 KB
    __shared__ unsigned            s_pack[TOK_PER_BLOCK / 4]; // 4 KB packed tokens
    __shared__ float4              s_prod[TPB];               // 4 KB per-thread products
    __shared__ bool                s_is_last;
    __shared__ float4              s_warp[TPB / 32];          // phase-3 use only

    const unsigned tid  = threadIdx.x;
    const unsigned lane = tid & 31u;
    const unsigned wid  = tid >> 5;
    const unsigned nblk = gridDim.x;

    // ── Stage tokens: 4 coalesced LDG.128 per thread (MLP=4); pack 4/word.
    const int4* __restrict__ tok4 = reinterpret_cast<const int4*>(tokens);
    const unsigned blk_i4 = blockIdx.x * (TOK_PER_BLOCK / 4);
    int4 a0 = tok4[blk_i4 + tid];
    int4 a1 = tok4[blk_i4 + tid + 256];
    int4 a2 = tok4[blk_i4 + tid + 512];
    int4 a3 = tok4[blk_i4 + tid + 768];

    // ── Replicated table build (rotated, conflict-free writes).
    if (tid < 128) {
        float4 e = reinterpret_cast<const float4*>(ls)[tid];
        #pragma unroll
        for (int r = 0; r < 8; r++) {
            unsigned r_eff = (r + tid) & 7u;
            *reinterpret_cast<float4*>(s_tab + tid * 128 + r_eff * 16) = e;
        }
    }

    s_pack[tid]       = (unsigned)a0.x | ((unsigned)a0.y << 8) | ((unsigned)a0.z << 16) | ((unsigned)a0.w << 24);
    s_pack[tid + 256] = (unsigned)a1.x | ((unsigned)a1.y << 8) | ((unsigned)a1.z << 16) | ((unsigned)a1.w << 24);
    s_pack[tid + 512] = (unsigned)a2.x | ((unsigned)a2.y << 8) | ((unsigned)a2.z << 16) | ((unsigned)a2.w << 24);
    s_pack[tid + 768] = (unsigned)a3.x | ((unsigned)a3.y << 8) | ((unsigned)a3.z << 16) | ((unsigned)a3.w << 24);
    __syncthreads();

    // ── Phase 1: 16 tokens via ONE LDS.128; four independent 4-token chains.
    const uint4 w = reinterpret_cast<const uint4*>(s_pack)[tid];
    const unsigned rbase = (lane & 7u) * 16u;

    #define TAB(word, sh) (*reinterpret_cast<const float4*>( \
        s_tab + ((((word) >> (sh)) & 127u) << 7) + rbase))

    float4 A = TAB(w.x, 0);
    float4 B = TAB(w.y, 0);
    float4 C = TAB(w.z, 0);
    float4 D = TAB(w.w, 0);
    A = mm2(A, TAB(w.x,  8));  B = mm2(B, TAB(w.y,  8));
    C = mm2(C, TAB(w.z,  8));  D = mm2(D, TAB(w.w,  8));
    A = mm2(A, TAB(w.x, 16));  B = mm2(B, TAB(w.y, 16));
    C = mm2(C, TAB(w.z, 16));  D = mm2(D, TAB(w.w, 16));
    A = mm2(A, TAB(w.x, 24));  B = mm2(B, TAB(w.y, 24));
    C = mm2(C, TAB(w.z, 24));  D = mm2(D, TAB(w.w, 24));
    float4 M = mm2(mm2(A, B), mm2(C, D));
    #undef TAB

    // ── Phase 2: dump products to smem; ONLY warp 0 reduces (no per-warp SHFL).
    s_prod[swz(tid)] = M;
    __syncthreads();

    if (wid == 0) {
        float4 p0 = s_prod[swz(8 * lane + 0)];
        float4 p1 = s_prod[swz(8 * lane + 1)];
        float4 p2 = s_prod[swz(8 * lane + 2)];
        float4 p3 = s_prod[swz(8 * lane + 3)];
        float4 p4 = s_prod[swz(8 * lane + 4)];
        float4 p5 = s_prod[swz(8 * lane + 5)];
        float4 p6 = s_prod[swz(8 * lane + 6)];
        float4 p7 = s_prod[swz(8 * lane + 7)];
        float4 a = mm2(p0, p1), b = mm2(p2, p3), c = mm2(p4, p5), d = mm2(p6, p7);
        float4 P = mm2(mm2(a, b), mm2(c, d));

        P = warp_reduce_ordered(P, lane);

        if (lane == 0) {
            g_part[blockIdx.x] = P;
            // Two-level completion counter (acq_rel; no L1 flush).
            const unsigned grp = blockIdx.x >> GROUP_SHIFT;
            bool last_here = false;
            unsigned o1 = atom_inc_acqrel(&g_cnt[grp * 64]);
            if (o1 == (1u << GROUP_SHIFT) - 1) {
                unsigned o2 = atom_inc_acqrel(&g_cnt[NGROUPS * 64]);
                last_here = (o2 == (nblk >> GROUP_SHIFT) - 1);
            }
            s_is_last = last_here;
        }
    }
    __syncthreads();

    // ── Phase 3: last block combines all 1024 partials in order.
    if (s_is_last) {
        const int base = tid * 4;

        float4 P0 = g_part[base + 0];
        float4 P1 = g_part[base + 1];
        float4 P2 = g_part[base + 2];
        float4 P3 = g_part[base + 3];
        float4 P  = mm2(mm2(P0, P1), mm2(P2, P3));

        P = warp_reduce_ordered(P, lane);
        if (lane == 0) s_warp[wid] = P;
        __syncthreads();

        if (tid == 0) {
            float4 R = s_warp[0];
            #pragma unroll
            for (int wI = 1; wI < TPB / 32; wI++) R = mm2(R, s_warp[wI]);

            // Faithful to reference: last token's matrix applied a second time.
            int last = tokens[n_tokens - 1];
            float4 L = *reinterpret_cast<const float4*>(s_tab + (last << 7));
            R = mm2(R, L);

            out[0] = R.x;   // v = [1,0] @ R -> row 0
            out[1] = R.y;
        }

        if (tid <= NGROUPS) atomicExch(&g_cnt[tid * 64], 0u);  // reset for replay
    }
}

extern "C" void kernel_launch(void* const* d_in, const int* in_sizes, int n_in,
                              void* d_out, int out_size) {
    const int*   tokens = (const int*)d_in[0];
    const float* ls     = (const float*)d_in[1];
    float* out = (float*)d_out;

    const int n = in_sizes[0];                 // 4194304
    const int nblocks = n / TOK_PER_BLOCK;     // 1024

    chain_fused_kernel<<<nblocks, TPB>>>(tokens, ls, out, n);
}

// round 10
// speedup vs baseline: 1.1684x; 1.1684x over previous
#include <cuda_runtime.h>

// tokens: int32[4194304] (values in [0,128)), ls: float32[128,2,2], final (unused)
// output: float32[2] = row 0 of ordered product of ls[tokens[t]], last token applied twice.

#define TPB 256
#define TOK_PER_THREAD 32
#define TOK_PER_BLOCK (TPB * TOK_PER_THREAD)   // 8192
#define MAX_BLOCKS 4096

__device__ float4 g_part[MAX_BLOCKS];
__device__ unsigned g_count = 0;

// C = A @ B, row-major 2x2 packed in float4 (x=m00, y=m01, z=m10, w=m11)
__device__ __forceinline__ float4 mm2(float4 A, float4 B) {
    float4 C;
    C.x = fmaf(A.x, B.x, A.y * B.z);
    C.y = fmaf(A.x, B.y, A.y * B.w);
    C.z = fmaf(A.z, B.x, A.w * B.z);
    C.w = fmaf(A.z, B.y, A.w * B.w);
    return C;
}

// Order-preserving pairwise warp reduction; lane 0 ends with ordered product.
__device__ __forceinline__ float4 warp_reduce_ordered(float4 M, unsigned lane) {
    #pragma unroll
    for (int off = 1; off < 32; off <<= 1) {
        float4 B;
        B.x = __shfl_down_sync(0xffffffffu, M.x, off);
        B.y = __shfl_down_sync(0xffffffffu, M.y, off);
        B.z = __shfl_down_sync(0xffffffffu, M.z, off);
        B.w = __shfl_down_sync(0xffffffffu, M.w, off);
        if ((lane & (2 * off - 1)) == 0) M = mm2(M, B);
    }
    return M;
}

__global__ void __launch_bounds__(TPB)
chain_fused_kernel(const int* __restrict__ tokens,
                   const float* __restrict__ ls,
                   float* __restrict__ out,
                   int n_tokens) {
    // Replicated table: entry j, replica r at byte j*128 + r*16.
    // Lane l reads replica (l&7) -> fixed bank group, uniform 4-way = floor.
    __shared__ __align__(16) char  s_tab[128 * 128];          // 16 KB
    __shared__ unsigned            s_pack[TOK_PER_BLOCK / 4]; // 8 KB packed tokens
    __shared__ float4              s_warp[TPB / 32];
    __shared__ bool                s_is_last;

    const unsigned tid  = threadIdx.x;
    const unsigned lane = tid & 31u;
    const unsigned wid  = tid >> 5;
    const unsigned nblk = gridDim.x;

    // ── Stage tokens: 8 coalesced LDG.128 per thread (MLP=8); pack 4 tokens
    //    per 32-bit word (values < 128 fit in a byte).
    const int4* __restrict__ tok4 = reinterpret_cast<const int4*>(tokens);
    const unsigned blk_i4 = blockIdx.x * (TOK_PER_BLOCK / 4);

    int4 a[8];
    #pragma unroll
    for (int k = 0; k < 8; k++) a[k] = tok4[blk_i4 + tid + 256 * k];

    // ── Replicated table build (rotated, conflict-free writes).
    if (tid < 128) {
        float4 e = reinterpret_cast<const float4*>(ls)[tid];
        #pragma unroll
        for (int r = 0; r < 8; r++) {
            unsigned r_eff = (r + tid) & 7u;
            *reinterpret_cast<float4*>(s_tab + tid * 128 + r_eff * 16) = e;
        }
    }

    #pragma unroll
    for (int k = 0; k < 8; k++) {
        s_pack[tid + 256 * k] = (unsigned)a[k].x | ((unsigned)a[k].y << 8)
                              | ((unsigned)a[k].z << 16) | ((unsigned)a[k].w << 24);
    }
    __syncthreads();

    // ── Phase 1: this thread's 32 contiguous tokens via TWO LDS.128;
    //    four independent 8-token chains, tree-combined (order preserved).
    const uint4 w0 = reinterpret_cast<const uint4*>(s_pack)[2 * tid];
    const uint4 w1 = reinterpret_cast<const uint4*>(s_pack)[2 * tid + 1];
    const unsigned rbase = (lane & 7u) * 16u;

    #define TAB(word, sh) (*reinterpret_cast<const float4*>( \
        s_tab + ((((word) >> (sh)) & 127u) << 7) + rbase))

    // Chain A: tokens 0-7 (w0.x, w0.y)   Chain B: tokens 8-15 (w0.z, w0.w)
    // Chain C: tokens 16-23 (w1.x, w1.y) Chain D: tokens 24-31 (w1.z, w1.w)
    float4 A = TAB(w0.x, 0);
    float4 B = TAB(w0.z, 0);
    float4 C = TAB(w1.x, 0);
    float4 D = TAB(w1.z, 0);
    A = mm2(A, TAB(w0.x,  8));  B = mm2(B, TAB(w0.z,  8));
    C = mm2(C, TAB(w1.x,  8));  D = mm2(D, TAB(w1.z,  8));
    A = mm2(A, TAB(w0.x, 16));  B = mm2(B, TAB(w0.z, 16));
    C = mm2(C, TAB(w1.x, 16));  D = mm2(D, TAB(w1.z, 16));
    A = mm2(A, TAB(w0.x, 24));  B = mm2(B, TAB(w0.z, 24));
    C = mm2(C, TAB(w1.x, 24));  D = mm2(D, TAB(w1.z, 24));
    A = mm2(A, TAB(w0.y,  0));  B = mm2(B, TAB(w0.w,  0));
    C = mm2(C, TAB(w1.y,  0));  D = mm2(D, TAB(w1.w,  0));
    A = mm2(A, TAB(w0.y,  8));  B = mm2(B, TAB(w0.w,  8));
    C = mm2(C, TAB(w1.y,  8));  D = mm2(D, TAB(w1.w,  8));
    A = mm2(A, TAB(w0.y, 16));  B = mm2(B, TAB(w0.w, 16));
    C = mm2(C, TAB(w1.y, 16));  D = mm2(D, TAB(w1.w, 16));
    A = mm2(A, TAB(w0.y, 24));  B = mm2(B, TAB(w0.w, 24));
    C = mm2(C, TAB(w1.y, 24));  D = mm2(D, TAB(w1.w, 24));
    float4 M = mm2(mm2(A, B), mm2(C, D));
    #undef TAB

    // ── Phase 2 (R6-style): per-warp ordered shuffle reduce -> block partial.
    M = warp_reduce_ordered(M, lane);
    if (lane == 0) s_warp[wid] = M;
    __syncthreads();

    if (tid == 0) {
        float4 R = s_warp[0];
        #pragma unroll
        for (int wI = 1; wI < TPB / 32; wI++) R = mm2(R, s_warp[wI]);
        g_part[blockIdx.x] = R;
        __threadfence();                      // publish partial before counting
        unsigned old = atomicAdd(&g_count, 1u);
        s_is_last = (old == nblk - 1);
    }
    __syncthreads();

    // ── Phase 3: last block combines all 512 partials in order.
    if (s_is_last) {
        __threadfence();
        const int base = tid * 2;             // 512/256 = 2 partials per thread

        float4 P0 = g_part[base + 0];
        float4 P1 = g_part[base + 1];
        float4 P  = mm2(P0, P1);

        P = warp_reduce_ordered(P, lane);
        if (lane == 0) s_warp[wid] = P;
        __syncthreads();

        if (tid == 0) {
            float4 R = s_warp[0];
            #pragma unroll
            for (int wI = 1; wI < TPB / 32; wI++) R = mm2(R, s_warp[wI]);

            // Faithful to reference: last token's matrix applied a second time.
            int last = tokens[n_tokens - 1];
            float4 L = *reinterpret_cast<const float4*>(s_tab + (last << 7));
            R = mm2(R, L);

            out[0] = R.x;   // v = [1,0] @ R -> row 0
            out[1] = R.y;

            atomicExch(&g_count, 0u);   // reset for next graph replay
        }
    }
}

extern "C" void kernel_launch(void* const* d_in, const int* in_sizes, int n_in,
                              void* d_out, int out_size) {
    const int*   tokens = (const int*)d_in[0];
    const float* ls     = (const float*)d_in[1];
    float* out = (float*)d_out;

    const int n = in_sizes[0];                 // 4194304
    const int nblocks = n / TOK_PER_BLOCK;     // 512

    chain_fused_kernel<<<nblocks, TPB>>>(tokens, ls, out, n);
}